// round 16
// baseline (speedup 1.0000x reference)
#include <cuda_runtime.h>
#include <math.h>

#define B_ 1024
#define H_ 512
#define V_ 128
#define T_ 67
#define TTHINK 17
#define NGEN 64

// ---------------- scratch (device globals; no allocations allowed) ----------
__device__ float g_hA[B_ * H_];
__device__ float g_hB[B_ * H_];
__device__ float g_hn[B_ * H_];
__device__ float g_cur[B_ * V_];    // dense cur (think step 0 only)
__device__ float g_wfcT[H_ * V_];   // w_fc transposed: [k][v]
__device__ int g_tok[B_];
__device__ int g_steps[B_];
__device__ unsigned char g_halted[B_];
__device__ int g_tilemax[B_ / 64];

// ---------------- reference tanh: MLIR math-polynomial-approximation --------
// FMA-contracted Horner, clamp +/-7.99881172180175781, |x|<0.0004 -> x
__device__ __forceinline__ float xla_tanh(float x) {
    const float c = 7.99881172180175781f;
    float xc = fminf(fmaxf(x, -c), c);
    float x2 = __fmul_rn(xc, xc);
    float p = -2.76076847742355e-16f;
    p = fmaf(x2, p, 2.00018790482477e-13f);
    p = fmaf(x2, p, -8.60467152213735e-11f);
    p = fmaf(x2, p, 5.12229709037114e-08f);
    p = fmaf(x2, p, 1.48572235717979e-05f);
    p = fmaf(x2, p, 6.37261928875436e-04f);
    p = fmaf(x2, p, 4.89352455891786e-03f);
    float num = __fmul_rn(xc, p);
    float q = 1.19825839466702e-06f;
    q = fmaf(x2, q, 1.18534705686654e-04f);
    q = fmaf(x2, q, 2.26843463243900e-03f);
    q = fmaf(x2, q, 4.89352518554385e-03f);
    float t = __fdiv_rn(num, q);
    return (fabsf(x) < 0.0004f) ? x : t;
}

__device__ __forceinline__ float logf_cr(float x) {
    return (float)log((double)x);
}
__device__ __forceinline__ float expf_cr(float x) {
    return (float)exp((double)x);
}

// ---------------- init ------------------------------------------------------
__global__ void init_kernel(const float* __restrict__ w_fc) {
    int idx = blockIdx.x * blockDim.x + threadIdx.x;
    if (idx < B_ * H_) g_hA[idx] = 0.0f;
    if (idx < H_ * V_) {
        int k = idx / V_;
        int v = idx % V_;
        g_wfcT[idx] = w_fc[v * H_ + k];
    }
    if (idx < B_) { g_steps[idx] = 0; g_halted[idx] = 0; }
}

__global__ void maxlen_kernel(const int* __restrict__ lengths) {
    __shared__ int s[64];
    int t = threadIdx.x;
    s[t] = lengths[blockIdx.x * 64 + t];
    __syncthreads();
    #pragma unroll
    for (int off = 32; off > 0; off >>= 1) {
        if (t < off) s[t] = max(s[t], s[t + off]);
        __syncthreads();
    }
    if (t == 0) g_tilemax[blockIdx.x] = s[0];
}

__global__ void gather_cur_kernel(const float* __restrict__ x,
                                  const int* __restrict__ lengths) {
    int idx = blockIdx.x * blockDim.x + threadIdx.x;
    if (idx < B_ * V_) {
        int b = idx / V_;
        int v = idx % V_;
        g_cur[idx] = x[(long)b * T_ * V_ + (long)(lengths[b] - 1) * V_ + v];
    }
}

// ---------------- RNN cell GEMM: 64x64 tile, 512 thr, BK=32, dbl-buffered ---
// Each output accumulated strictly ascending-k as one serial fmaf chain
// (identical arithmetic to the validated R15 kernel).
__device__ __forceinline__ void gemm_seg(
    const float* __restrict__ Abase, long arstride,
    const float* __restrict__ W, int kTot,
    float acc[2][4], int b0, int j0, int tid,
    float (*As)[68], float (*Bs)[68])
{
    int la_r = tid >> 3;            // 0..63
    int la_k = (tid & 7) << 2;      // 0,4,...,28
    int tr = tid >> 4;              // 0..31
    int tc = tid & 15;              // 0..15

    const float* aptr = Abase + (long)(b0 + la_r) * arstride + la_k;
    const float* bptr = W + (long)(j0 + la_r) * kTot + la_k;

    // prologue: stage tile 0
    float4 av = *(const float4*)(aptr);
    float4 bv = *(const float4*)(bptr);
    As[la_k + 0][la_r] = av.x; As[la_k + 1][la_r] = av.y;
    As[la_k + 2][la_r] = av.z; As[la_k + 3][la_r] = av.w;
    Bs[la_k + 0][la_r] = bv.x; Bs[la_k + 1][la_r] = bv.y;
    Bs[la_k + 2][la_r] = bv.z; Bs[la_k + 3][la_r] = bv.w;
    __syncthreads();

    int nT = kTot >> 5;
    for (int t = 0; t < nT; t++) {
        float4 av2, bv2;
        if (t + 1 < nT) {
            av2 = *(const float4*)(aptr + (t + 1) * 32);
            bv2 = *(const float4*)(bptr + (t + 1) * 32);
        }
        #pragma unroll
        for (int k = 0; k < 32; k++) {
            float a0 = As[k][tr * 2 + 0];
            float a1 = As[k][tr * 2 + 1];
            float4 b = *(const float4*)(&Bs[k][tc * 4]);
            acc[0][0] = fmaf(a0, b.x, acc[0][0]);
            acc[0][1] = fmaf(a0, b.y, acc[0][1]);
            acc[0][2] = fmaf(a0, b.z, acc[0][2]);
            acc[0][3] = fmaf(a0, b.w, acc[0][3]);
            acc[1][0] = fmaf(a1, b.x, acc[1][0]);
            acc[1][1] = fmaf(a1, b.y, acc[1][1]);
            acc[1][2] = fmaf(a1, b.z, acc[1][2]);
            acc[1][3] = fmaf(a1, b.w, acc[1][3]);
        }
        __syncthreads();
        if (t + 1 < nT) {
            As[la_k + 0][la_r] = av2.x; As[la_k + 1][la_r] = av2.y;
            As[la_k + 2][la_r] = av2.z; As[la_k + 3][la_r] = av2.w;
            Bs[la_k + 0][la_r] = bv2.x; Bs[la_k + 1][la_r] = bv2.y;
            Bs[la_k + 2][la_r] = bv2.z; Bs[la_k + 3][la_r] = bv2.w;
        }
        __syncthreads();
    }
}

// h_out[b,j] = xla_tanh(((x@w_ih.T + b_ih) + h@w_hh.T) + b_hh)
__global__ __launch_bounds__(512) void cell_kernel(
    const float* __restrict__ Abase, long arstride,
    const int* __restrict__ tok,
    const float* __restrict__ h_in,
    float* __restrict__ h_out,
    const float* __restrict__ w_ih, const float* __restrict__ w_hh,
    const float* __restrict__ b_ih, const float* __restrict__ b_hh,
    const int* __restrict__ lengths, int mask_t)
{
    int b0 = blockIdx.x * 64;
    int j0 = blockIdx.y * 64;
    int tid = threadIdx.x;

    if (mask_t >= 0 && mask_t >= g_tilemax[blockIdx.x]) {
        for (int i = tid; i < 64 * 16; i += 512) {
            int r = i >> 4;
            int c4 = (i & 15) << 2;
            *(float4*)&h_out[(long)(b0 + r) * H_ + j0 + c4] =
                *(const float4*)&h_in[(long)(b0 + r) * H_ + j0 + c4];
        }
        return;
    }

    __shared__ __align__(16) float As[32][68];
    __shared__ __align__(16) float Bs[32][68];

    float accX[2][4] = {};
    float accH[2][4] = {};

    if (tok == nullptr) {
        gemm_seg(Abase, arstride, w_ih, V_, accX, b0, j0, tid, As, Bs);
    }
    gemm_seg(h_in, H_, w_hh, H_, accH, b0, j0, tid, As, Bs);

    int tr = tid >> 4;
    int tc = tid & 15;
    #pragma unroll
    for (int m = 0; m < 2; m++) {
        int b = b0 + tr * 2 + m;
        int keep = 0;
        if (mask_t >= 0) keep = (mask_t >= lengths[b]);
        int tkm = tok ? tok[b] : 0;
        float4 o;
        float ov[4];
        #pragma unroll
        for (int n = 0; n < 4; n++) {
            int j = j0 + tc * 4 + n;
            float dx = tok ? w_ih[(long)j * V_ + tkm] : accX[m][n];
            float v = __fadd_rn(__fadd_rn(__fadd_rn(dx, b_ih[j]), accH[m][n]), b_hh[j]);
            v = xla_tanh(v);
            if (keep) v = h_in[(long)b * H_ + j];
            ov[n] = v;
        }
        o.x = ov[0]; o.y = ov[1]; o.z = ov[2]; o.w = ov[3];
        *(float4*)&h_out[(long)b * H_ + j0 + tc * 4] = o;
    }
}

// ---------------- logits + gumbel + softmax-argmax + state update -----------
// 4 rows/block (grid 256), 256 threads. vg = tid&127, half = tid>>7 owns
// rows half*2 .. half*2+1. Dot serial ascending-k. Softmax-argmax emulation:
// zmax parallel fmaxf (exact), serial-ascending sum, per-lane fdiv + ballot
// first-match scan (same predicates and first index as the serial version).
#define RROWS 4

__global__ __launch_bounds__(256) void logits_kernel(
    const float* __restrict__ hn,
    float* __restrict__ h,               // think: h update where active; gen: null
    const float* __restrict__ b_fc,
    const float* __restrict__ u,
    int last_step,
    int think_mode,
    float* __restrict__ out, int gen_n)
{
    int b0 = blockIdx.x * RROWS;
    int tid = threadIdx.x;
    int vg = tid & 127;
    int half = tid >> 7;
    int rbase = half * 2;
    int warpInHalf = (tid >> 5) & 3;

    __shared__ __align__(16) float sh[RROWS][H_];
    __shared__ float se[RROWS][V_];      // exp(z - zmax)
    __shared__ float szw[RROWS][4];      // per-warp zmax partials
    __shared__ float szmax[RROWS];
    __shared__ float ssum[RROWS];
    __shared__ float symax[RROWS];
    __shared__ unsigned int sball[RROWS][4];
    __shared__ int sh_flag[RROWS];
    __shared__ int sh_tok[RROWS];

    for (int i = tid; i < RROWS * (H_ / 4); i += 256) {
        int r = i >> 7;
        int c = (i & 127) << 2;
        *(float4*)&sh[r][c] = *(const float4*)&hn[(long)(b0 + r) * H_ + c];
    }
    __syncthreads();

    // serial ascending-k dot per output (2 rows per thread)
    float acc[2] = {0.0f, 0.0f};
    for (int k = 0; k < H_; k += 4) {
        float w0 = g_wfcT[(k + 0) * V_ + vg];
        float w1 = g_wfcT[(k + 1) * V_ + vg];
        float w2 = g_wfcT[(k + 2) * V_ + vg];
        float w3 = g_wfcT[(k + 3) * V_ + vg];
        #pragma unroll
        for (int j = 0; j < 2; j++) {
            float4 hv = *(const float4*)&sh[rbase + j][k];
            acc[j] = fmaf(hv.x, w0, acc[j]);
            acc[j] = fmaf(hv.y, w1, acc[j]);
            acc[j] = fmaf(hv.z, w2, acc[j]);
            acc[j] = fmaf(hv.w, w3, acc[j]);
        }
    }

    // z = (logit + bias) + gumbel; zmax via warp fmaxf reduce (exact)
    float bf = b_fc[vg];
    float zv[2];
    #pragma unroll
    for (int j = 0; j < 2; j++) {
        int r = rbase + j;
        int b = b0 + r;
        float logit = __fadd_rn(acc[j], bf);
        float uv = u[(long)b * V_ + vg];
        float a1 = __fadd_rn(uv, 1e-10f);
        float l1 = logf_cr(a1);
        float a2 = __fadd_rn(-l1, 1e-10f);
        float g = -logf_cr(a2);
        zv[j] = __fadd_rn(logit, g);
        float zm = zv[j];
        #pragma unroll
        for (int off = 16; off > 0; off >>= 1)
            zm = fmaxf(zm, __shfl_xor_sync(0xffffffffu, zm, off));
        if ((tid & 31) == 0) szw[r][warpInHalf] = zm;
    }
    __syncthreads();

    if (tid < RROWS)
        szmax[tid] = fmaxf(fmaxf(szw[tid][0], szw[tid][1]),
                           fmaxf(szw[tid][2], szw[tid][3]));
    __syncthreads();

    // e = exp_cr(z - zmax)
    #pragma unroll
    for (int j = 0; j < 2; j++) {
        int r = rbase + j;
        se[r][vg] = expf_cr(__fadd_rn(zv[j], -szmax[r]));
    }
    __syncthreads();

    // serial ascending softmax sum + emax; ymax = fl(emax / s)
    if (tid < RROWS) {
        int r = tid;
        float s = 0.0f;
        float emax = se[r][0];
        for (int v = 0; v < V_; v++) {
            s = __fadd_rn(s, se[r][v]);
            if (se[r][v] > emax) emax = se[r][v];
        }
        ssum[r] = s;
        symax[r] = __fdiv_rn(emax, s);
    }
    __syncthreads();

    // parallel first-match: lane predicate fl(e/s)==ymax, ballot, scan
    #pragma unroll
    for (int j = 0; j < 2; j++) {
        int r = rbase + j;
        float dv = __fdiv_rn(se[r][vg], ssum[r]);
        unsigned int ball = __ballot_sync(0xffffffffu, dv == symax[r]);
        if ((tid & 31) == 0) sball[r][warpInHalf] = ball;
    }
    __syncthreads();

    if (tid < RROWS) {
        int r = tid;
        int b = b0 + r;
        int tk = 0;
        #pragma unroll
        for (int w = 0; w < 4; w++) {
            unsigned int bl = sball[r][w];
            if (bl) { tk = w * 32 + __ffs(bl) - 1; break; }
        }
        sh_tok[r] = tk;
        if (think_mode) {
            int act = (g_halted[b] == 0);
            sh_flag[r] = act;
            if (act) {
                g_steps[b] += 1;
                g_tok[b] = tk;
                if (tk == V_ - 1 || last_step) g_halted[b] = 1;
            }
        } else {
            sh_flag[r] = 0;
            g_tok[b] = tk;
            if (tk < V_ - 1)
                out[((long)b * NGEN + gen_n) * (V_ - 1) + tk] = 1.0f;
        }
    }
    __syncthreads();

    // h <- hn where active (think only); bit-exact copy
    if (h) {
        for (int i = tid; i < RROWS * (H_ / 4); i += 256) {
            int r = i >> 7;
            int c = (i & 127) << 2;
            if (sh_flag[r])
                *(float4*)&h[(long)(b0 + r) * H_ + c] =
                    *(const float4*)&hn[(long)(b0 + r) * H_ + c];
        }
    }
}

__global__ void steps_out_kernel(float* __restrict__ out, long off, long total) {
    int b = blockIdx.x * blockDim.x + threadIdx.x;
    if (b < B_ && off + b < total) out[off + b] = (float)g_steps[b];
}

// ---------------- launch ----------------------------------------------------
extern "C" void kernel_launch(void* const* d_in, const int* in_sizes, int n_in,
                              void* d_out, int out_size) {
    const float* x       = (const float*)d_in[0];
    const int*   lengths = (const int*)d_in[1];
    const float* w_ih    = (const float*)d_in[2];
    const float* w_hh    = (const float*)d_in[3];
    const float* b_ih    = (const float*)d_in[4];
    const float* b_hh    = (const float*)d_in[5];
    const float* w_fc    = (const float*)d_in[6];
    const float* b_fc    = (const float*)d_in[7];
    const float* u_think = (const float*)d_in[8];
    const float* u_gen   = (const float*)d_in[9];
    float* out = (float*)d_out;

    float *hA, *hB, *hn, *cur;
    int *tok;
    cudaGetSymbolAddress((void**)&hA, g_hA);
    cudaGetSymbolAddress((void**)&hB, g_hB);
    cudaGetSymbolAddress((void**)&hn, g_hn);
    cudaGetSymbolAddress((void**)&cur, g_cur);
    cudaGetSymbolAddress((void**)&tok, g_tok);

    cudaMemsetAsync(d_out, 0, (size_t)out_size * sizeof(float), 0);
    init_kernel<<<2048, 256>>>(w_fc);
    maxlen_kernel<<<B_ / 64, 64>>>(lengths);
    gather_cur_kernel<<<(B_ * V_ + 255) / 256, 256>>>(x, lengths);

    dim3 cgrid(B_ / 64, H_ / 64);

    // ---- encoder: ping-pong hA <-> hB ----
    const float* hin = hA;
    float* hout = hB;
    for (int t = 0; t < T_; t++) {
        cell_kernel<<<cgrid, 512>>>(x + (long)t * V_, (long)T_ * V_, nullptr,
                                    hin, hout, w_ih, w_hh, b_ih, b_hh,
                                    lengths, t);
        const float* tmp = hout;
        hout = (float*)hin;
        hin = tmp;
    }
    float* hstate = (float*)hin;
    float* spare = hout;

    // ---- think loop ----
    for (int k = 0; k < TTHINK; k++) {
        if (k == 0) {
            cell_kernel<<<cgrid, 512>>>(cur, (long)V_, nullptr,
                                        hstate, hn, w_ih, w_hh, b_ih, b_hh,
                                        nullptr, -1);
        } else {
            cell_kernel<<<cgrid, 512>>>(nullptr, 0, tok,
                                        hstate, hn, w_ih, w_hh, b_ih, b_hh,
                                        nullptr, -1);
        }
        logits_kernel<<<B_ / RROWS, 256>>>(hn, hstate, b_fc,
                                           u_think + (long)k * B_ * V_,
                                           (k == TTHINK - 1) ? 1 : 0,
                                           1, nullptr, 0);
    }

    steps_out_kernel<<<4, 256>>>(out, (long)B_ * NGEN * (V_ - 1), (long)out_size);

    // ---- generation ----
    float* bufs[2] = { spare, hn };
    const float* gin = hstate;
    for (int n = 0; n < NGEN; n++) {
        float* gout = bufs[n & 1];
        cell_kernel<<<cgrid, 512>>>(nullptr, 0, tok,
                                    gin, gout, w_ih, w_hh, b_ih, b_hh,
                                    nullptr, -1);
        logits_kernel<<<B_ / RROWS, 256>>>(gout, nullptr, b_fc,
                                           u_gen + (long)n * B_ * V_,
                                           0, 0, out, n);
        gin = gout;
    }
}

// round 17
// speedup vs baseline: 1.7335x; 1.7335x over previous
#include <cuda_runtime.h>
#include <math.h>

#define B_ 1024
#define H_ 512
#define V_ 128
#define T_ 67
#define TTHINK 17
#define NGEN 64

// ---------------- scratch (device globals; no allocations allowed) ----------
__device__ float g_hA[B_ * H_];
__device__ float g_hB[B_ * H_];
__device__ float g_hn[B_ * H_];
__device__ float g_cur[B_ * V_];    // dense cur (think step 0 only)
__device__ float g_wfcT[H_ * V_];   // w_fc transposed: [k][v]
__device__ int g_tok[B_];
__device__ int g_steps[B_];
__device__ unsigned char g_halted[B_];
__device__ int g_tilemax[B_ / 64];

// ---------------- reference tanh: MLIR math-polynomial-approximation --------
// FMA-contracted Horner, clamp +/-7.99881172180175781, |x|<0.0004 -> x
__device__ __forceinline__ float xla_tanh(float x) {
    const float c = 7.99881172180175781f;
    float xc = fminf(fmaxf(x, -c), c);
    float x2 = __fmul_rn(xc, xc);
    float p = -2.76076847742355e-16f;
    p = fmaf(x2, p, 2.00018790482477e-13f);
    p = fmaf(x2, p, -8.60467152213735e-11f);
    p = fmaf(x2, p, 5.12229709037114e-08f);
    p = fmaf(x2, p, 1.48572235717979e-05f);
    p = fmaf(x2, p, 6.37261928875436e-04f);
    p = fmaf(x2, p, 4.89352455891786e-03f);
    float num = __fmul_rn(xc, p);
    float q = 1.19825839466702e-06f;
    q = fmaf(x2, q, 1.18534705686654e-04f);
    q = fmaf(x2, q, 2.26843463243900e-03f);
    q = fmaf(x2, q, 4.89352518554385e-03f);
    float t = __fdiv_rn(num, q);
    return (fabsf(x) < 0.0004f) ? x : t;
}

__device__ __forceinline__ float logf_cr(float x) {
    return (float)log((double)x);
}
__device__ __forceinline__ float expf_cr(float x) {
    return (float)exp((double)x);
}

// ---------------- init ------------------------------------------------------
__global__ void init_kernel(const float* __restrict__ w_fc) {
    int idx = blockIdx.x * blockDim.x + threadIdx.x;
    if (idx < B_ * H_) g_hA[idx] = 0.0f;
    if (idx < H_ * V_) {
        int k = idx / V_;
        int v = idx % V_;
        g_wfcT[idx] = w_fc[v * H_ + k];
    }
    if (idx < B_) { g_steps[idx] = 0; g_halted[idx] = 0; }
}

__global__ void maxlen_kernel(const int* __restrict__ lengths) {
    __shared__ int s[64];
    int t = threadIdx.x;
    s[t] = lengths[blockIdx.x * 64 + t];
    __syncthreads();
    #pragma unroll
    for (int off = 32; off > 0; off >>= 1) {
        if (t < off) s[t] = max(s[t], s[t + off]);
        __syncthreads();
    }
    if (t == 0) g_tilemax[blockIdx.x] = s[0];
}

__global__ void gather_cur_kernel(const float* __restrict__ x,
                                  const int* __restrict__ lengths) {
    int idx = blockIdx.x * blockDim.x + threadIdx.x;
    if (idx < B_ * V_) {
        int b = idx / V_;
        int v = idx % V_;
        g_cur[idx] = x[(long)b * T_ * V_ + (long)(lengths[b] - 1) * V_ + v];
    }
}

// ---------------- RNN cell GEMM: 64x64 tile, 256 thr, 4x4 rtile, BK=32 ------
// Double-buffered smem (ping-pong), register prefetch, ONE sync per tile.
// Each output is one strictly ascending-k serial fmaf chain — identical
// arithmetic to the validated R15 kernel.
__device__ __forceinline__ void gemm_seg(
    const float* __restrict__ Abase, long arstride,
    const float* __restrict__ W, int kTot,
    float acc[4][4], int b0, int j0, int tid,
    float (*As)[32][68], float (*Bs)[32][68])
{
    int la_r = tid >> 2;            // 0..63
    int la_c = (tid & 3) << 3;      // 0,8,16,24
    int tr = tid >> 4;              // 0..15
    int tc = tid & 15;              // 0..15

    const float* aptr = Abase + (long)(b0 + la_r) * arstride + la_c;
    const float* bptr = W + (long)(j0 + la_r) * kTot + la_c;

    // stage tile 0 into buffer 0
    float4 pa0 = *(const float4*)(aptr);
    float4 pa1 = *(const float4*)(aptr + 4);
    float4 pb0 = *(const float4*)(bptr);
    float4 pb1 = *(const float4*)(bptr + 4);
    As[0][la_c + 0][la_r] = pa0.x; As[0][la_c + 1][la_r] = pa0.y;
    As[0][la_c + 2][la_r] = pa0.z; As[0][la_c + 3][la_r] = pa0.w;
    As[0][la_c + 4][la_r] = pa1.x; As[0][la_c + 5][la_r] = pa1.y;
    As[0][la_c + 6][la_r] = pa1.z; As[0][la_c + 7][la_r] = pa1.w;
    Bs[0][la_c + 0][la_r] = pb0.x; Bs[0][la_c + 1][la_r] = pb0.y;
    Bs[0][la_c + 2][la_r] = pb0.z; Bs[0][la_c + 3][la_r] = pb0.w;
    Bs[0][la_c + 4][la_r] = pb1.x; Bs[0][la_c + 5][la_r] = pb1.y;
    Bs[0][la_c + 6][la_r] = pb1.z; Bs[0][la_c + 7][la_r] = pb1.w;
    __syncthreads();

    int nT = kTot >> 5;
    for (int t = 0; t < nT; t++) {
        int s = t & 1;
        if (t + 1 < nT) {
            const float* ap = aptr + (t + 1) * 32;
            const float* bp = bptr + (t + 1) * 32;
            pa0 = *(const float4*)(ap);
            pa1 = *(const float4*)(ap + 4);
            pb0 = *(const float4*)(bp);
            pb1 = *(const float4*)(bp + 4);
        }
        #pragma unroll
        for (int k = 0; k < 32; k++) {
            float4 a = *(const float4*)(&As[s][k][tr * 4]);
            float4 b = *(const float4*)(&Bs[s][k][tc * 4]);
            float av[4] = {a.x, a.y, a.z, a.w};
            float bw[4] = {b.x, b.y, b.z, b.w};
            #pragma unroll
            for (int m = 0; m < 4; m++)
                #pragma unroll
                for (int n = 0; n < 4; n++)
                    acc[m][n] = fmaf(av[m], bw[n], acc[m][n]);
        }
        if (t + 1 < nT) {
            int s2 = s ^ 1;
            As[s2][la_c + 0][la_r] = pa0.x; As[s2][la_c + 1][la_r] = pa0.y;
            As[s2][la_c + 2][la_r] = pa0.z; As[s2][la_c + 3][la_r] = pa0.w;
            As[s2][la_c + 4][la_r] = pa1.x; As[s2][la_c + 5][la_r] = pa1.y;
            As[s2][la_c + 6][la_r] = pa1.z; As[s2][la_c + 7][la_r] = pa1.w;
            Bs[s2][la_c + 0][la_r] = pb0.x; Bs[s2][la_c + 1][la_r] = pb0.y;
            Bs[s2][la_c + 2][la_r] = pb0.z; Bs[s2][la_c + 3][la_r] = pb0.w;
            Bs[s2][la_c + 4][la_r] = pb1.x; Bs[s2][la_c + 5][la_r] = pb1.y;
            Bs[s2][la_c + 6][la_r] = pb1.z; Bs[s2][la_c + 7][la_r] = pb1.w;
        }
        __syncthreads();
    }
}

// h_out[b,j] = xla_tanh(((x@w_ih.T + b_ih) + h@w_hh.T) + b_hh)
__global__ __launch_bounds__(256) void cell_kernel(
    const float* __restrict__ Abase, long arstride,
    const int* __restrict__ tok,
    const float* __restrict__ h_in,
    float* __restrict__ h_out,
    const float* __restrict__ w_ih, const float* __restrict__ w_hh,
    const float* __restrict__ b_ih, const float* __restrict__ b_hh,
    const int* __restrict__ lengths, int mask_t)
{
    int b0 = blockIdx.x * 64;
    int j0 = blockIdx.y * 64;
    int tid = threadIdx.x;

    if (mask_t >= 0 && mask_t >= g_tilemax[blockIdx.x]) {
        for (int i = tid; i < 64 * 16; i += 256) {
            int r = i >> 4;
            int c4 = (i & 15) << 2;
            *(float4*)&h_out[(long)(b0 + r) * H_ + j0 + c4] =
                *(const float4*)&h_in[(long)(b0 + r) * H_ + j0 + c4];
        }
        return;
    }

    __shared__ __align__(16) float As[2][32][68];
    __shared__ __align__(16) float Bs[2][32][68];

    float accX[4][4] = {};
    float accH[4][4] = {};

    if (tok == nullptr) {
        gemm_seg(Abase, arstride, w_ih, V_, accX, b0, j0, tid, As, Bs);
    }
    gemm_seg(h_in, H_, w_hh, H_, accH, b0, j0, tid, As, Bs);

    int tr = tid >> 4;
    int tc = tid & 15;
    #pragma unroll
    for (int m = 0; m < 4; m++) {
        int b = b0 + tr * 4 + m;
        int keep = 0;
        if (mask_t >= 0) keep = (mask_t >= lengths[b]);
        int tkm = tok ? tok[b] : 0;
        float ov[4];
        #pragma unroll
        for (int n = 0; n < 4; n++) {
            int j = j0 + tc * 4 + n;
            float dx = tok ? w_ih[(long)j * V_ + tkm] : accX[m][n];
            float v = __fadd_rn(__fadd_rn(__fadd_rn(dx, b_ih[j]), accH[m][n]), b_hh[j]);
            v = xla_tanh(v);
            if (keep) v = h_in[(long)b * H_ + j];
            ov[n] = v;
        }
        float4 o; o.x = ov[0]; o.y = ov[1]; o.z = ov[2]; o.w = ov[3];
        *(float4*)&h_out[(long)b * H_ + j0 + tc * 4] = o;
    }
}

// ---------------- logits + gumbel + softmax-argmax + state update -----------
// (byte-identical to the R16-validated version)
#define RROWS 4

__global__ __launch_bounds__(256) void logits_kernel(
    const float* __restrict__ hn,
    float* __restrict__ h,               // think: h update where active; gen: null
    const float* __restrict__ b_fc,
    const float* __restrict__ u,
    int last_step,
    int think_mode,
    float* __restrict__ out, int gen_n)
{
    int b0 = blockIdx.x * RROWS;
    int tid = threadIdx.x;
    int vg = tid & 127;
    int half = tid >> 7;
    int rbase = half * 2;
    int warpInHalf = (tid >> 5) & 3;

    __shared__ __align__(16) float sh[RROWS][H_];
    __shared__ float se[RROWS][V_];      // exp(z - zmax)
    __shared__ float szw[RROWS][4];      // per-warp zmax partials
    __shared__ float szmax[RROWS];
    __shared__ float ssum[RROWS];
    __shared__ float symax[RROWS];
    __shared__ unsigned int sball[RROWS][4];
    __shared__ int sh_flag[RROWS];
    __shared__ int sh_tok[RROWS];

    for (int i = tid; i < RROWS * (H_ / 4); i += 256) {
        int r = i >> 7;
        int c = (i & 127) << 2;
        *(float4*)&sh[r][c] = *(const float4*)&hn[(long)(b0 + r) * H_ + c];
    }
    __syncthreads();

    // serial ascending-k dot per output (2 rows per thread)
    float acc[2] = {0.0f, 0.0f};
    for (int k = 0; k < H_; k += 4) {
        float w0 = g_wfcT[(k + 0) * V_ + vg];
        float w1 = g_wfcT[(k + 1) * V_ + vg];
        float w2 = g_wfcT[(k + 2) * V_ + vg];
        float w3 = g_wfcT[(k + 3) * V_ + vg];
        #pragma unroll
        for (int j = 0; j < 2; j++) {
            float4 hv = *(const float4*)&sh[rbase + j][k];
            acc[j] = fmaf(hv.x, w0, acc[j]);
            acc[j] = fmaf(hv.y, w1, acc[j]);
            acc[j] = fmaf(hv.z, w2, acc[j]);
            acc[j] = fmaf(hv.w, w3, acc[j]);
        }
    }

    // z = (logit + bias) + gumbel; zmax via warp fmaxf reduce (exact)
    float bf = b_fc[vg];
    float zv[2];
    #pragma unroll
    for (int j = 0; j < 2; j++) {
        int r = rbase + j;
        int b = b0 + r;
        float logit = __fadd_rn(acc[j], bf);
        float uv = u[(long)b * V_ + vg];
        float a1 = __fadd_rn(uv, 1e-10f);
        float l1 = logf_cr(a1);
        float a2 = __fadd_rn(-l1, 1e-10f);
        float g = -logf_cr(a2);
        zv[j] = __fadd_rn(logit, g);
        float zm = zv[j];
        #pragma unroll
        for (int off = 16; off > 0; off >>= 1)
            zm = fmaxf(zm, __shfl_xor_sync(0xffffffffu, zm, off));
        if ((tid & 31) == 0) szw[r][warpInHalf] = zm;
    }
    __syncthreads();

    if (tid < RROWS)
        szmax[tid] = fmaxf(fmaxf(szw[tid][0], szw[tid][1]),
                           fmaxf(szw[tid][2], szw[tid][3]));
    __syncthreads();

    // e = exp_cr(z - zmax)
    #pragma unroll
    for (int j = 0; j < 2; j++) {
        int r = rbase + j;
        se[r][vg] = expf_cr(__fadd_rn(zv[j], -szmax[r]));
    }
    __syncthreads();

    // serial ascending softmax sum + emax; ymax = fl(emax / s)
    if (tid < RROWS) {
        int r = tid;
        float s = 0.0f;
        float emax = se[r][0];
        for (int v = 0; v < V_; v++) {
            s = __fadd_rn(s, se[r][v]);
            if (se[r][v] > emax) emax = se[r][v];
        }
        ssum[r] = s;
        symax[r] = __fdiv_rn(emax, s);
    }
    __syncthreads();

    // parallel first-match: lane predicate fl(e/s)==ymax, ballot, scan
    #pragma unroll
    for (int j = 0; j < 2; j++) {
        int r = rbase + j;
        float dv = __fdiv_rn(se[r][vg], ssum[r]);
        unsigned int ball = __ballot_sync(0xffffffffu, dv == symax[r]);
        if ((tid & 31) == 0) sball[r][warpInHalf] = ball;
    }
    __syncthreads();

    if (tid < RROWS) {
        int r = tid;
        int b = b0 + r;
        int tk = 0;
        #pragma unroll
        for (int w = 0; w < 4; w++) {
            unsigned int bl = sball[r][w];
            if (bl) { tk = w * 32 + __ffs(bl) - 1; break; }
        }
        sh_tok[r] = tk;
        if (think_mode) {
            int act = (g_halted[b] == 0);
            sh_flag[r] = act;
            if (act) {
                g_steps[b] += 1;
                g_tok[b] = tk;
                if (tk == V_ - 1 || last_step) g_halted[b] = 1;
            }
        } else {
            sh_flag[r] = 0;
            g_tok[b] = tk;
            if (tk < V_ - 1)
                out[((long)b * NGEN + gen_n) * (V_ - 1) + tk] = 1.0f;
        }
    }
    __syncthreads();

    // h <- hn where active (think only); bit-exact copy
    if (h) {
        for (int i = tid; i < RROWS * (H_ / 4); i += 256) {
            int r = i >> 7;
            int c = (i & 127) << 2;
            if (sh_flag[r])
                *(float4*)&h[(long)(b0 + r) * H_ + c] =
                    *(const float4*)&hn[(long)(b0 + r) * H_ + c];
        }
    }
}

__global__ void steps_out_kernel(float* __restrict__ out, long off, long total) {
    int b = blockIdx.x * blockDim.x + threadIdx.x;
    if (b < B_ && off + b < total) out[off + b] = (float)g_steps[b];
}

// ---------------- launch ----------------------------------------------------
extern "C" void kernel_launch(void* const* d_in, const int* in_sizes, int n_in,
                              void* d_out, int out_size) {
    const float* x       = (const float*)d_in[0];
    const int*   lengths = (const int*)d_in[1];
    const float* w_ih    = (const float*)d_in[2];
    const float* w_hh    = (const float*)d_in[3];
    const float* b_ih    = (const float*)d_in[4];
    const float* b_hh    = (const float*)d_in[5];
    const float* w_fc    = (const float*)d_in[6];
    const float* b_fc    = (const float*)d_in[7];
    const float* u_think = (const float*)d_in[8];
    const float* u_gen   = (const float*)d_in[9];
    float* out = (float*)d_out;

    float *hA, *hB, *hn, *cur;
    int *tok;
    cudaGetSymbolAddress((void**)&hA, g_hA);
    cudaGetSymbolAddress((void**)&hB, g_hB);
    cudaGetSymbolAddress((void**)&hn, g_hn);
    cudaGetSymbolAddress((void**)&cur, g_cur);
    cudaGetSymbolAddress((void**)&tok, g_tok);

    cudaMemsetAsync(d_out, 0, (size_t)out_size * sizeof(float), 0);
    init_kernel<<<2048, 256>>>(w_fc);
    maxlen_kernel<<<B_ / 64, 64>>>(lengths);
    gather_cur_kernel<<<(B_ * V_ + 255) / 256, 256>>>(x, lengths);

    dim3 cgrid(B_ / 64, H_ / 64);

    // ---- encoder: ping-pong hA <-> hB ----
    const float* hin = hA;
    float* hout = hB;
    for (int t = 0; t < T_; t++) {
        cell_kernel<<<cgrid, 256>>>(x + (long)t * V_, (long)T_ * V_, nullptr,
                                    hin, hout, w_ih, w_hh, b_ih, b_hh,
                                    lengths, t);
        const float* tmp = hout;
        hout = (float*)hin;
        hin = tmp;
    }
    float* hstate = (float*)hin;
    float* spare = hout;

    // ---- think loop ----
    for (int k = 0; k < TTHINK; k++) {
        if (k == 0) {
            cell_kernel<<<cgrid, 256>>>(cur, (long)V_, nullptr,
                                        hstate, hn, w_ih, w_hh, b_ih, b_hh,
                                        nullptr, -1);
        } else {
            cell_kernel<<<cgrid, 256>>>(nullptr, 0, tok,
                                        hstate, hn, w_ih, w_hh, b_ih, b_hh,
                                        nullptr, -1);
        }
        logits_kernel<<<B_ / RROWS, 256>>>(hn, hstate, b_fc,
                                           u_think + (long)k * B_ * V_,
                                           (k == TTHINK - 1) ? 1 : 0,
                                           1, nullptr, 0);
    }

    steps_out_kernel<<<4, 256>>>(out, (long)B_ * NGEN * (V_ - 1), (long)out_size);

    // ---- generation ----
    float* bufs[2] = { spare, hn };
    const float* gin = hstate;
    for (int n = 0; n < NGEN; n++) {
        float* gout = bufs[n & 1];
        cell_kernel<<<cgrid, 256>>>(nullptr, 0, tok,
                                    gin, gout, w_ih, w_hh, b_ih, b_hh,
                                    nullptr, -1);
        logits_kernel<<<B_ / RROWS, 256>>>(gout, nullptr, b_fc,
                                           u_gen + (long)n * B_ * V_,
                                           0, 0, out, n);
        gin = gout;
    }
}